// round 1
// baseline (speedup 1.0000x reference)
#include <cuda_runtime.h>
#include <cuda_bf16.h>

// GDLoss: elementwise Gaussian KL-distance loss over [N,5] xywhr boxes.
// loss = 1 - 1/(TAU + sqrt(max(dis, EPS))), dis = term1 + term2 - 2.
// Memory-bound: 176MB traffic. Strategy: smem-stage the AoS [*,5] rows with
// fully coalesced loads, compute per-thread from conflict-free stride-5 smem.

#define TAU_F   1.0f
#define EPS_F   1e-6f
#define BLK     256

__global__ void __launch_bounds__(BLK) gd_loss_kernel(
    const float* __restrict__ pred,
    const float* __restrict__ target,
    float* __restrict__ out,
    int n)
{
    __shared__ float sp[BLK * 5];
    __shared__ float st[BLK * 5];

    const int tid = threadIdx.x;
    const long long blockBase = (long long)blockIdx.x * BLK;
    int nb = n - (int)blockBase;
    if (nb > BLK) nb = BLK;
    if (nb <= 0) return;
    const int nfloats = nb * 5;

    const float* __restrict__ pbase = pred   + blockBase * 5;
    const float* __restrict__ tbase = target + blockBase * 5;

    // Coalesced cooperative load of this block's 5*nb floats (stride BLK).
    #pragma unroll
    for (int k = 0; k < 5; ++k) {
        int i = tid + k * BLK;
        if (i < nfloats) {
            sp[i] = pbase[i];
            st[i] = tbase[i];
        }
    }
    __syncthreads();

    if (tid < nb) {
        // stride-5 smem reads: gcd(5,32)=1 -> bank-conflict-free
        const float px = sp[5 * tid + 0];
        const float py = sp[5 * tid + 1];
        float pw = sp[5 * tid + 2];
        float ph = sp[5 * tid + 3];
        const float prr = sp[5 * tid + 4];

        const float tx = st[5 * tid + 0];
        const float ty = st[5 * tid + 1];
        float tw = st[5 * tid + 2];
        float th = st[5 * tid + 3];
        const float trr = st[5 * tid + 4];

        // clip wh
        pw = fminf(fmaxf(pw, 1e-7f), 1e7f);
        ph = fminf(fmaxf(ph, 1e-7f), 1e7f);
        tw = fminf(fmaxf(tw, 1e-7f), 1e7f);
        th = fminf(fmaxf(th, 1e-7f), 1e7f);

        float cp, spn, ct, stn;
        __sincosf(prr, &spn, &cp);
        __sincosf(trr, &stn, &ct);

        // sigma components: sigma = R diag((w/2)^2,(h/2)^2) R^T
        const float pa = 0.25f * pw * pw;
        const float pb = 0.25f * ph * ph;
        const float p11 = pa * cp * cp + pb * spn * spn;
        const float p12 = (pa - pb) * spn * cp;
        const float p22 = pa * spn * spn + pb * cp * cp;

        const float ta = 0.25f * tw * tw;
        const float tb = 0.25f * th * th;
        const float t11 = ta * ct * ct + tb * stn * stn;
        const float t12 = (ta - tb) * stn * ct;
        const float t22 = ta * stn * stn + tb * ct * ct;

        const float det_p = p11 * p22 - p12 * p12;
        const float det_t = t11 * t22 - t12 * t12;

        const float dx = px - tx;
        const float dy = py - ty;

        const float inv_det_t = __frcp_rn(det_t);

        const float term1 = (t22 * dx * dx - 2.0f * t12 * dx * dy + t11 * dy * dy) * inv_det_t;
        const float trace_term = (t22 * p11 - 2.0f * t12 * p12 + t11 * p22) * inv_det_t;
        const float term2 = trace_term + __logf(det_t * __frcp_rn(det_p));

        float dis = term1 + term2 - 2.0f;
        float kl = fmaxf(dis, EPS_F);
        float loss = 1.0f - __frcp_rn(TAU_F + sqrtf(kl));

        out[blockBase + tid] = loss;
    }
}

extern "C" void kernel_launch(void* const* d_in, const int* in_sizes, int n_in,
                              void* d_out, int out_size)
{
    const float* pred   = (const float*)d_in[0];
    const float* target = (const float*)d_in[1];
    // d_in[2] (weight) is unused by the reference computation (LOSS_WEIGHT=1).
    float* out = (float*)d_out;

    const int n = out_size;  // N boxes, output is [N,1] floats
    const int grid = (n + BLK - 1) / BLK;
    gd_loss_kernel<<<grid, BLK>>>(pred, target, out, n);
}